// round 14
// baseline (speedup 1.0000x reference)
#include <cuda_runtime.h>
#include <cuda_fp16.h>
#include <cstdint>

// ============================================================================
// MonteCarloNet: out[m,n] = sum_g Wf[g] * tanh(mask2 * 2 * sum_f
//                  (mask1 * t1[n,f]) * W2[g,f]),  t1[n,f]=tanh(2 in[n] W1[f])
// (keep-scales folded: layer-1 scale into t1 arg, layer-2 x2 into W2.)
// Masks: bit-exact JAX threefry2x32 partitionable (CONFIRMED, rel 4.3e-6 at
// fp32), key(42); draw_i = block(km,0,i).o0 ^ .o1 ; keep <=> MSB==0.
// Matvec: packed fma.rn.f32x2 (R7). Threefry: pure SHF rounds (R8/R9 pipe
// migrations regressed). R12 software pipeline CONFIRMED (1126->1055us).
// R13's __byte_perm sign-mode selector FAILED (intrinsic contract is nibbles
// 0-7 only) -- mask build reverted to R12's proven SHR/SHR/PRMT form.
// R14: R12 + #pragma unroll 2 on the gp loop (the only delta).
// ============================================================================

#define NMC   1024
#define SEQ   2048
#define NF    64
#define TB    128            // threads per block (over n)
#define MPB   8              // m samples per block

typedef unsigned long long ull;

union PackF2 { ull u; float2 f; unsigned w[2]; };

struct KP { unsigned a, b; };

__host__ __device__ constexpr unsigned rotl32c(unsigned x, int d) {
  return (x << d) | (x >> (32 - d));
}
__host__ __device__ constexpr KP tf_block_c(unsigned k0, unsigned k1,
                                            unsigned x0, unsigned x1) {
  unsigned ks[3] = {k0, k1, k0 ^ k1 ^ 0x1BD11BDAu};
  int rot[2][4] = {{13, 15, 26, 6}, {17, 29, 16, 24}};
  x0 += ks[0]; x1 += ks[1];
  for (int g = 0; g < 5; ++g) {
    for (int j = 0; j < 4; ++j) {
      x0 += x1; x1 = rotl32c(x1, rot[g & 1][j]); x1 ^= x0;
    }
    x0 += ks[(g + 1) % 3];
    x1 += ks[(g + 2) % 3] + (unsigned)(g + 1);
  }
  return {x0, x1};
}
constexpr KP KM1 = tf_block_c(0u, 42u, 0u, 0u);
constexpr KP KM2 = tf_block_c(0u, 42u, 0u, 1u);

// Pure-SHF round (R7-proven; do not move ops across pipes -- see R8/R9).
#define TF_R(d) { x0 += x1; x1 = __funnelshift_l(x1, x1, d) ^ x0; }

template<unsigned K0, unsigned K1>
__device__ __forceinline__ unsigned rng_draw(unsigned i) {
  constexpr unsigned K2 = K0 ^ K1 ^ 0x1BD11BDAu;
  unsigned x0 = K0, x1 = i + K1;
  TF_R(13) TF_R(15) TF_R(26) TF_R(6)    x0 += K1; x1 += K2 + 1u;
  TF_R(17) TF_R(29) TF_R(16) TF_R(24)   x0 += K2; x1 += K0 + 2u;
  TF_R(13) TF_R(15) TF_R(26) TF_R(6)    x0 += K0; x1 += K1 + 3u;
  TF_R(17) TF_R(29) TF_R(16) TF_R(24)   x0 += K1; x1 += K2 + 4u;
  TF_R(13) TF_R(15) TF_R(26) TF_R(6)    x0 += K2; x1 += K0 + 5u;
  return x0 ^ x1;
}

// keep <=> MSB(r)==0. Branch-free AND masking (tanh(0)=0 makes this exact).
__device__ __forceinline__ float mask_apply(float v, unsigned r) {
  unsigned km = ~(unsigned)((int)r >> 31);
  return __uint_as_float(__float_as_uint(v) & km);
}
// half2 KEEP mask: low 16 bits from r0's keep, high 16 from r1's keep.
// (R12-proven. Do NOT use sign-mode selectors with __byte_perm -- R13.)
__device__ __forceinline__ unsigned mask_h2(unsigned r0, unsigned r1) {
  unsigned s0 = ~(unsigned)((int)r0 >> 31);
  unsigned s1 = ~(unsigned)((int)r1 >> 31);
  return __byte_perm(s0, s1, 0x5410);
}
__device__ __forceinline__ float tanh_fast(float x) {
  float y; asm("tanh.approx.f32 %0, %1;" : "=f"(y) : "f"(x)); return y;
}

// ---- packed f32x2 arithmetic (base sm_100 ISA; operands are plain b64) ----
__device__ __forceinline__ void ffma2(ull& d, ull a, ull b) {
  asm("fma.rn.f32x2 %0, %1, %2, %0;" : "+l"(d) : "l"(a), "l"(b));
}
__device__ __forceinline__ ull addf2(ull a, ull b) {
  ull d; asm("add.rn.f32x2 %0, %1, %2;" : "=l"(d) : "l"(a), "l"(b));
  return d;
}

// ---------------------------------------------------------------------------
// Prologue kernel: packed t1 pairs, transposed:
//   g_t1p[fp*SEQ + n] = half2( t1[n,2fp], t1[n,2fp+1] )
// ---------------------------------------------------------------------------
__device__ unsigned g_t1p[(NF / 2) * SEQ];

__global__ void t1_kernel(const float* __restrict__ input,
                          const float* __restrict__ W1) {
  int i = blockIdx.x * blockDim.x + threadIdx.x;   // over 32*2048
  int fp = i >> 11, n = i & (SEQ - 1);
  float x = 2.0f * input[n];
  __half2 h = __floats2half2_rn(tanhf(x * W1[2 * fp]), tanhf(x * W1[2 * fp + 1]));
  g_t1p[i] = *reinterpret_cast<unsigned*>(&h);
}

// ---------------------------------------------------------------------------
// Fused phase-2 + next-tile-mask1 generation. GEN=false for the last tile.
// sX1 slots are per-thread private: the caller read all 32 before any store.
// ---------------------------------------------------------------------------
template<bool GEN>
__device__ __forceinline__ float phase2_fn(
    unsigned base, unsigned basen, const ull (&x1p)[NF / 2],
    const float* __restrict__ sW2, const float* __restrict__ sWf,
    unsigned* __restrict__ sX1, const unsigned* __restrict__ t1col, int tid) {
  float oacc = 0.0f;
#pragma unroll 2
  for (int gp = 0; gp < NF / 2; ++gp) {
    const int gA = 2 * gp, gB = 2 * gp + 1;
    // mask2 chains for this tile (start early, 160-cyc latency each)
    unsigned rA = rng_draw<KM2.a, KM2.b>(base + (unsigned)gA);
    unsigned rB = rng_draw<KM2.a, KM2.b>(base + (unsigned)gB);

    // next tile's mask1 pair (feature pair fp == gp), staged to smem
    unsigned stage = 0;
    if (GEN) {
      unsigned r0 = rng_draw<KM1.a, KM1.b>(basen + 2 * (unsigned)gp);
      unsigned r1 = rng_draw<KM1.a, KM1.b>(basen + 2 * (unsigned)gp + 1);
      unsigned hp = __ldg(&t1col[gp * SEQ]);
      stage = hp & mask_h2(r0, r1);
    }

    const ulonglong2* rowA = reinterpret_cast<const ulonglong2*>(sW2 + gA * NF);
    const ulonglong2* rowB = reinterpret_cast<const ulonglong2*>(sW2 + gB * NF);
    ull a0 = 0, a1 = 0, b0 = 0, b1 = 0;
#pragma unroll
    for (int q = 0; q < 16; ++q) {
      ulonglong2 wa = rowA[q];
      ulonglong2 wb = rowB[q];
      if (q & 1) {
        ffma2(a1, x1p[2 * q + 0], wa.x);
        ffma2(b1, x1p[2 * q + 0], wb.x);
        ffma2(a1, x1p[2 * q + 1], wa.y);
        ffma2(b1, x1p[2 * q + 1], wb.y);
      } else {
        ffma2(a0, x1p[2 * q + 0], wa.x);
        ffma2(b0, x1p[2 * q + 0], wb.x);
        ffma2(a0, x1p[2 * q + 1], wa.y);
        ffma2(b0, x1p[2 * q + 1], wb.y);
      }
    }
    if (GEN) sX1[gp * TB + tid] = stage;

    PackF2 sA; sA.u = addf2(a0, a1);
    PackF2 sB; sB.u = addf2(b0, b1);
    float xA = sA.f.x + sA.f.y;              // *2 folded into W2
    float xB = sB.f.x + sB.f.y;
    float yA = mask_apply(tanh_fast(xA), rA);
    float yB = mask_apply(tanh_fast(xB), rB);
    oacc = fmaf(yA, sWf[gA], oacc);
    oacc = fmaf(yB, sWf[gB], oacc);
  }
  return oacc;
}

// ---------------------------------------------------------------------------
// Main fused kernel. 128 n-lanes x MPB m-samples per block.
// smem: W2 fp32 pre-doubled 16KB + x1 staging 16KB + Wf 256B ~= 33KB.
// t1 pairs come from gmem via __ldg (16KB/block, L1-resident across mi).
// ---------------------------------------------------------------------------
__global__ void __launch_bounds__(TB, 5)
mc_kernel(const float* __restrict__ W2,
          const float* __restrict__ Wf,
          float* __restrict__ out) {
  __shared__ __align__(16) float    sW2[NF * NF];       // [g][f], x2 pre-folded
  __shared__ __align__(16) unsigned sX1[(NF / 2) * TB]; // staged masked half2
  __shared__ __align__(16) float    sWf[NF];

  const int tid = threadIdx.x;
  const int n0  = blockIdx.x * TB;
  const int m0  = blockIdx.y * MPB;
  const int n   = n0 + tid;
  const unsigned* t1col = g_t1p + n;    // t1col[fp*SEQ] = pair fp for this n

  // W2 -> shared fp32, pre-doubled
  {
    const float4* src = reinterpret_cast<const float4*>(W2);
    float4* dst = reinterpret_cast<float4*>(sW2);
#pragma unroll 1
    for (int i = tid; i < NF * NF / 4; i += TB) {
      float4 v = src[i];
      v.x *= 2.0f; v.y *= 2.0f; v.z *= 2.0f; v.w *= 2.0f;
      dst[i] = v;
    }
  }
  if (tid < NF) sWf[tid] = Wf[tid];
  __syncthreads();

  // Pipeline prologue: stage mask1 for tile mi=0 (rolled; dynamic STS ok)
  {
    const unsigned base0 = ((unsigned)m0 * SEQ + (unsigned)n) * NF;
#pragma unroll 1
    for (int fp = 0; fp < NF / 2; ++fp) {
      unsigned r0 = rng_draw<KM1.a, KM1.b>(base0 + 2 * (unsigned)fp);
      unsigned r1 = rng_draw<KM1.a, KM1.b>(base0 + 2 * (unsigned)fp + 1);
      unsigned hp = __ldg(&t1col[fp * SEQ]);
      sX1[fp * TB + tid] = hp & mask_h2(r0, r1);
    }
  }
  // no sync: sX1 slots are per-thread private

#pragma unroll 1
  for (int mi = 0; mi < MPB; ++mi) {
    const unsigned m = (unsigned)(m0 + mi);
    const unsigned base  = (m * SEQ + (unsigned)n) * NF;
    const unsigned basen = base + (unsigned)(SEQ * NF);   // tile mi+1, same n

    // Load this tile's x1 from staging -> packed f32x2 registers
    ull x1p[NF / 2];
#pragma unroll
    for (int fp = 0; fp < NF / 2; ++fp) {
      unsigned hp = sX1[fp * TB + tid];
      PackF2 cv;
      cv.f = __half22float2(*reinterpret_cast<__half2*>(&hp));
      x1p[fp] = cv.u;
    }

    float oacc;
    if (mi != MPB - 1)
      oacc = phase2_fn<true>(base, basen, x1p, sW2, sWf, sX1, t1col, tid);
    else
      oacc = phase2_fn<false>(base, basen, x1p, sW2, sWf, sX1, t1col, tid);
    out[m * SEQ + (unsigned)n] = oacc;
  }
}

// ---------------------------------------------------------------------------
extern "C" void kernel_launch(void* const* d_in, const int* in_sizes, int n_in,
                              void* d_out, int out_size) {
  const float* input = (const float*)d_in[0];   // [2048,1]
  const float* W1    = (const float*)d_in[1];   // [64,1]
  const float* W2    = (const float*)d_in[2];   // [64,64]
  const float* Wf    = (const float*)d_in[3];   // [1,64]
  float* out         = (float*)d_out;           // [1024,2048,1]

  t1_kernel<<<((NF / 2) * SEQ) / 256, 256>>>(input, W1);
  mc_kernel<<<dim3(SEQ / TB, NMC / MPB), TB>>>(W2, Wf, out);
}

// round 15
// speedup vs baseline: 1.0216x; 1.0216x over previous
#include <cuda_runtime.h>
#include <cuda_fp16.h>
#include <cstdint>

// ============================================================================
// MonteCarloNet: out[m,n] = sum_g Wf[g] * tanh(mask2 * 2 * sum_f
//                  (mask1 * t1[n,f]) * W2[g,f]),  t1[n,f]=tanh(2 in[n] W1[f])
// (keep-scales folded: layer-1 scale into t1 arg, layer-2 x2 into W2.)
// Masks: bit-exact JAX threefry2x32 partitionable (CONFIRMED, rel 4.3e-6 at
// fp32), key(42); draw_i = block(km,0,i).o0 ^ .o1 ; keep <=> MSB==0.
//
// FINAL (R12 configuration, 1055us):
//  - packed fma.rn.f32x2 matvec (R7)
//  - pure-SHF threefry rounds (R8/R9 pipe migrations REGRESSED)
//  - R12 software pipeline: mask1 draws for tile mi+1 generated inside tile
//    mi's matvec loop (phase blending; the single biggest win, -6.3%)
//  - gp loop rolled: unroll 2 REGRESSED (R14); PRMT sign-mode FAILED (R13)
//  - 5 blocks/SM (R11 showed 6 regresses; R3 showed 4->5 ~neutral)
// ALU pipe measured ~94% of per-SMSP cap; threefry is the irreducible floor.
// ============================================================================

#define NMC   1024
#define SEQ   2048
#define NF    64
#define TB    128            // threads per block (over n)
#define MPB   8              // m samples per block

typedef unsigned long long ull;

union PackF2 { ull u; float2 f; unsigned w[2]; };

struct KP { unsigned a, b; };

__host__ __device__ constexpr unsigned rotl32c(unsigned x, int d) {
  return (x << d) | (x >> (32 - d));
}
__host__ __device__ constexpr KP tf_block_c(unsigned k0, unsigned k1,
                                            unsigned x0, unsigned x1) {
  unsigned ks[3] = {k0, k1, k0 ^ k1 ^ 0x1BD11BDAu};
  int rot[2][4] = {{13, 15, 26, 6}, {17, 29, 16, 24}};
  x0 += ks[0]; x1 += ks[1];
  for (int g = 0; g < 5; ++g) {
    for (int j = 0; j < 4; ++j) {
      x0 += x1; x1 = rotl32c(x1, rot[g & 1][j]); x1 ^= x0;
    }
    x0 += ks[(g + 1) % 3];
    x1 += ks[(g + 2) % 3] + (unsigned)(g + 1);
  }
  return {x0, x1};
}
constexpr KP KM1 = tf_block_c(0u, 42u, 0u, 0u);
constexpr KP KM2 = tf_block_c(0u, 42u, 0u, 1u);

// Pure-SHF round (R7-proven; do not move ops across pipes -- see R8/R9).
#define TF_R(d) { x0 += x1; x1 = __funnelshift_l(x1, x1, d) ^ x0; }

template<unsigned K0, unsigned K1>
__device__ __forceinline__ unsigned rng_draw(unsigned i) {
  constexpr unsigned K2 = K0 ^ K1 ^ 0x1BD11BDAu;
  unsigned x0 = K0, x1 = i + K1;
  TF_R(13) TF_R(15) TF_R(26) TF_R(6)    x0 += K1; x1 += K2 + 1u;
  TF_R(17) TF_R(29) TF_R(16) TF_R(24)   x0 += K2; x1 += K0 + 2u;
  TF_R(13) TF_R(15) TF_R(26) TF_R(6)    x0 += K0; x1 += K1 + 3u;
  TF_R(17) TF_R(29) TF_R(16) TF_R(24)   x0 += K1; x1 += K2 + 4u;
  TF_R(13) TF_R(15) TF_R(26) TF_R(6)    x0 += K2; x1 += K0 + 5u;
  return x0 ^ x1;
}

// keep <=> MSB(r)==0. Branch-free AND masking (tanh(0)=0 makes this exact).
__device__ __forceinline__ float mask_apply(float v, unsigned r) {
  unsigned km = ~(unsigned)((int)r >> 31);
  return __uint_as_float(__float_as_uint(v) & km);
}
// half2 KEEP mask: low 16 bits from r0's keep, high 16 from r1's keep.
// (R12-proven. Do NOT use sign-mode selectors with __byte_perm -- R13.)
__device__ __forceinline__ unsigned mask_h2(unsigned r0, unsigned r1) {
  unsigned s0 = ~(unsigned)((int)r0 >> 31);
  unsigned s1 = ~(unsigned)((int)r1 >> 31);
  return __byte_perm(s0, s1, 0x5410);
}
__device__ __forceinline__ float tanh_fast(float x) {
  float y; asm("tanh.approx.f32 %0, %1;" : "=f"(y) : "f"(x)); return y;
}

// ---- packed f32x2 arithmetic (base sm_100 ISA; operands are plain b64) ----
__device__ __forceinline__ void ffma2(ull& d, ull a, ull b) {
  asm("fma.rn.f32x2 %0, %1, %2, %0;" : "+l"(d) : "l"(a), "l"(b));
}
__device__ __forceinline__ ull addf2(ull a, ull b) {
  ull d; asm("add.rn.f32x2 %0, %1, %2;" : "=l"(d) : "l"(a), "l"(b));
  return d;
}

// ---------------------------------------------------------------------------
// Prologue kernel: packed t1 pairs, transposed:
//   g_t1p[fp*SEQ + n] = half2( t1[n,2fp], t1[n,2fp+1] )
// ---------------------------------------------------------------------------
__device__ unsigned g_t1p[(NF / 2) * SEQ];

__global__ void t1_kernel(const float* __restrict__ input,
                          const float* __restrict__ W1) {
  int i = blockIdx.x * blockDim.x + threadIdx.x;   // over 32*2048
  int fp = i >> 11, n = i & (SEQ - 1);
  float x = 2.0f * input[n];
  __half2 h = __floats2half2_rn(tanhf(x * W1[2 * fp]), tanhf(x * W1[2 * fp + 1]));
  g_t1p[i] = *reinterpret_cast<unsigned*>(&h);
}

// ---------------------------------------------------------------------------
// Fused phase-2 + next-tile-mask1 generation. GEN=false for the last tile.
// sX1 slots are per-thread private: the caller read all 32 before any store.
// ---------------------------------------------------------------------------
template<bool GEN>
__device__ __forceinline__ float phase2_fn(
    unsigned base, unsigned basen, const ull (&x1p)[NF / 2],
    const float* __restrict__ sW2, const float* __restrict__ sWf,
    unsigned* __restrict__ sX1, const unsigned* __restrict__ t1col, int tid) {
  float oacc = 0.0f;
#pragma unroll 1
  for (int gp = 0; gp < NF / 2; ++gp) {
    const int gA = 2 * gp, gB = 2 * gp + 1;
    // mask2 chains for this tile (start early, 160-cyc latency each)
    unsigned rA = rng_draw<KM2.a, KM2.b>(base + (unsigned)gA);
    unsigned rB = rng_draw<KM2.a, KM2.b>(base + (unsigned)gB);

    // next tile's mask1 pair (feature pair fp == gp), staged to smem
    unsigned stage = 0;
    if (GEN) {
      unsigned r0 = rng_draw<KM1.a, KM1.b>(basen + 2 * (unsigned)gp);
      unsigned r1 = rng_draw<KM1.a, KM1.b>(basen + 2 * (unsigned)gp + 1);
      unsigned hp = __ldg(&t1col[gp * SEQ]);
      stage = hp & mask_h2(r0, r1);
    }

    const ulonglong2* rowA = reinterpret_cast<const ulonglong2*>(sW2 + gA * NF);
    const ulonglong2* rowB = reinterpret_cast<const ulonglong2*>(sW2 + gB * NF);
    ull a0 = 0, a1 = 0, b0 = 0, b1 = 0;
#pragma unroll
    for (int q = 0; q < 16; ++q) {
      ulonglong2 wa = rowA[q];
      ulonglong2 wb = rowB[q];
      if (q & 1) {
        ffma2(a1, x1p[2 * q + 0], wa.x);
        ffma2(b1, x1p[2 * q + 0], wb.x);
        ffma2(a1, x1p[2 * q + 1], wa.y);
        ffma2(b1, x1p[2 * q + 1], wb.y);
      } else {
        ffma2(a0, x1p[2 * q + 0], wa.x);
        ffma2(b0, x1p[2 * q + 0], wb.x);
        ffma2(a0, x1p[2 * q + 1], wa.y);
        ffma2(b0, x1p[2 * q + 1], wb.y);
      }
    }
    if (GEN) sX1[gp * TB + tid] = stage;

    PackF2 sA; sA.u = addf2(a0, a1);
    PackF2 sB; sB.u = addf2(b0, b1);
    float xA = sA.f.x + sA.f.y;              // *2 folded into W2
    float xB = sB.f.x + sB.f.y;
    float yA = mask_apply(tanh_fast(xA), rA);
    float yB = mask_apply(tanh_fast(xB), rB);
    oacc = fmaf(yA, sWf[gA], oacc);
    oacc = fmaf(yB, sWf[gB], oacc);
  }
  return oacc;
}

// ---------------------------------------------------------------------------
// Main fused kernel. 128 n-lanes x MPB m-samples per block.
// smem: W2 fp32 pre-doubled 16KB + x1 staging 16KB + Wf 256B ~= 33KB.
// t1 pairs come from gmem via __ldg (16KB/block, L1-resident across mi).
// ---------------------------------------------------------------------------
__global__ void __launch_bounds__(TB, 5)
mc_kernel(const float* __restrict__ W2,
          const float* __restrict__ Wf,
          float* __restrict__ out) {
  __shared__ __align__(16) float    sW2[NF * NF];       // [g][f], x2 pre-folded
  __shared__ __align__(16) unsigned sX1[(NF / 2) * TB]; // staged masked half2
  __shared__ __align__(16) float    sWf[NF];

  const int tid = threadIdx.x;
  const int n0  = blockIdx.x * TB;
  const int m0  = blockIdx.y * MPB;
  const int n   = n0 + tid;
  const unsigned* t1col = g_t1p + n;    // t1col[fp*SEQ] = pair fp for this n

  // W2 -> shared fp32, pre-doubled
  {
    const float4* src = reinterpret_cast<const float4*>(W2);
    float4* dst = reinterpret_cast<float4*>(sW2);
#pragma unroll 1
    for (int i = tid; i < NF * NF / 4; i += TB) {
      float4 v = src[i];
      v.x *= 2.0f; v.y *= 2.0f; v.z *= 2.0f; v.w *= 2.0f;
      dst[i] = v;
    }
  }
  if (tid < NF) sWf[tid] = Wf[tid];
  __syncthreads();

  // Pipeline prologue: stage mask1 for tile mi=0 (rolled; dynamic STS ok)
  {
    const unsigned base0 = ((unsigned)m0 * SEQ + (unsigned)n) * NF;
#pragma unroll 1
    for (int fp = 0; fp < NF / 2; ++fp) {
      unsigned r0 = rng_draw<KM1.a, KM1.b>(base0 + 2 * (unsigned)fp);
      unsigned r1 = rng_draw<KM1.a, KM1.b>(base0 + 2 * (unsigned)fp + 1);
      unsigned hp = __ldg(&t1col[fp * SEQ]);
      sX1[fp * TB + tid] = hp & mask_h2(r0, r1);
    }
  }
  // no sync: sX1 slots are per-thread private

#pragma unroll 1
  for (int mi = 0; mi < MPB; ++mi) {
    const unsigned m = (unsigned)(m0 + mi);
    const unsigned base  = (m * SEQ + (unsigned)n) * NF;
    const unsigned basen = base + (unsigned)(SEQ * NF);   // tile mi+1, same n

    // Load this tile's x1 from staging -> packed f32x2 registers
    ull x1p[NF / 2];
#pragma unroll
    for (int fp = 0; fp < NF / 2; ++fp) {
      unsigned hp = sX1[fp * TB + tid];
      PackF2 cv;
      cv.f = __half22float2(*reinterpret_cast<__half2*>(&hp));
      x1p[fp] = cv.u;
    }

    float oacc;
    if (mi != MPB - 1)
      oacc = phase2_fn<true>(base, basen, x1p, sW2, sWf, sX1, t1col, tid);
    else
      oacc = phase2_fn<false>(base, basen, x1p, sW2, sWf, sX1, t1col, tid);
    out[m * SEQ + (unsigned)n] = oacc;
  }
}

// ---------------------------------------------------------------------------
extern "C" void kernel_launch(void* const* d_in, const int* in_sizes, int n_in,
                              void* d_out, int out_size) {
  const float* input = (const float*)d_in[0];   // [2048,1]
  const float* W1    = (const float*)d_in[1];   // [64,1]
  const float* W2    = (const float*)d_in[2];   // [64,64]
  const float* Wf    = (const float*)d_in[3];   // [1,64]
  float* out         = (float*)d_out;           // [1024,2048,1]

  t1_kernel<<<((NF / 2) * SEQ) / 256, 256>>>(input, W1);
  mc_kernel<<<dim3(SEQ / TB, NMC / MPB), TB>>>(W2, Wf, out);
}

// round 17
// speedup vs baseline: 1.0281x; 1.0063x over previous
#include <cuda_runtime.h>
#include <cstdint>

// ============================================================================
// MonteCarloNet: out[m,n] = sum_g Wf[g] * tanh(mask2 * 2 * sum_f
//                  (mask1 * t1[n,f]) * W2[g,f]),  t1[n,f]=tanh(2 in[n] W1[f])
// (keep-scales folded: layer-1 scale into t1 arg, layer-2 x2 into W2.)
// Masks: bit-exact JAX threefry2x32 partitionable (CONFIRMED), key(42);
// draw_i = block(km,0,i).o0 ^ .o1 ; keep <=> MSB==0.
//
// Config: R12 software pipeline + fma.rn.f32x2 matvec + pure-SHF threefry
// (R8/R9 pipe migrations regressed; R13 PRMT failed; R14 unroll2 regressed;
// R11 6-block regressed).
// R17 = R16 (fp32 staging, no F2F converts) with Wf via __ldg instead of
// smem: static smem limit is 0xc000 and W2(16K)+sX1(32K)+Wf(256B) was 0x100
// over. Now exactly 0xc000 -> 4 blocks/SM.
// ============================================================================

#define NMC   1024
#define SEQ   2048
#define NF    64
#define TB    128            // threads per block (over n)
#define MPB   8              // m samples per block

typedef unsigned long long ull;

union PackF2 { ull u; float2 f; unsigned w[2]; };

struct KP { unsigned a, b; };

__host__ __device__ constexpr unsigned rotl32c(unsigned x, int d) {
  return (x << d) | (x >> (32 - d));
}
__host__ __device__ constexpr KP tf_block_c(unsigned k0, unsigned k1,
                                            unsigned x0, unsigned x1) {
  unsigned ks[3] = {k0, k1, k0 ^ k1 ^ 0x1BD11BDAu};
  int rot[2][4] = {{13, 15, 26, 6}, {17, 29, 16, 24}};
  x0 += ks[0]; x1 += ks[1];
  for (int g = 0; g < 5; ++g) {
    for (int j = 0; j < 4; ++j) {
      x0 += x1; x1 = rotl32c(x1, rot[g & 1][j]); x1 ^= x0;
    }
    x0 += ks[(g + 1) % 3];
    x1 += ks[(g + 2) % 3] + (unsigned)(g + 1);
  }
  return {x0, x1};
}
constexpr KP KM1 = tf_block_c(0u, 42u, 0u, 0u);
constexpr KP KM2 = tf_block_c(0u, 42u, 0u, 1u);

// Pure-SHF round (R7-proven; do not move ops across pipes -- see R8/R9).
#define TF_R(d) { x0 += x1; x1 = __funnelshift_l(x1, x1, d) ^ x0; }

template<unsigned K0, unsigned K1>
__device__ __forceinline__ unsigned rng_draw(unsigned i) {
  constexpr unsigned K2 = K0 ^ K1 ^ 0x1BD11BDAu;
  unsigned x0 = K0, x1 = i + K1;
  TF_R(13) TF_R(15) TF_R(26) TF_R(6)    x0 += K1; x1 += K2 + 1u;
  TF_R(17) TF_R(29) TF_R(16) TF_R(24)   x0 += K2; x1 += K0 + 2u;
  TF_R(13) TF_R(15) TF_R(26) TF_R(6)    x0 += K0; x1 += K1 + 3u;
  TF_R(17) TF_R(29) TF_R(16) TF_R(24)   x0 += K1; x1 += K2 + 4u;
  TF_R(13) TF_R(15) TF_R(26) TF_R(6)    x0 += K2; x1 += K0 + 5u;
  return x0 ^ x1;
}

// keep <=> MSB(r)==0. Branch-free AND masking (tanh(0)=0 makes this exact).
__device__ __forceinline__ float mask_apply(float v, unsigned r) {
  unsigned km = ~(unsigned)((int)r >> 31);
  return __uint_as_float(__float_as_uint(v) & km);
}
__device__ __forceinline__ float tanh_fast(float x) {
  float y; asm("tanh.approx.f32 %0, %1;" : "=f"(y) : "f"(x)); return y;
}

// ---- packed f32x2 arithmetic (base sm_100 ISA; operands are plain b64) ----
__device__ __forceinline__ void ffma2(ull& d, ull a, ull b) {
  asm("fma.rn.f32x2 %0, %1, %2, %0;" : "+l"(d) : "l"(a), "l"(b));
}
__device__ __forceinline__ ull addf2(ull a, ull b) {
  ull d; asm("add.rn.f32x2 %0, %1, %2;" : "=l"(d) : "l"(a), "l"(b));
  return d;
}

// ---------------------------------------------------------------------------
// Prologue kernel: packed fp32 t1 pairs, transposed:
//   g_t1f[fp*SEQ + n] = (f32 t1[n,2fp], f32 t1[n,2fp+1]) packed in one u64
// ---------------------------------------------------------------------------
__device__ ull g_t1f[(NF / 2) * SEQ];

__global__ void t1_kernel(const float* __restrict__ input,
                          const float* __restrict__ W1) {
  int i = blockIdx.x * blockDim.x + threadIdx.x;   // over 32*2048
  int fp = i >> 11, n = i & (SEQ - 1);
  float x = 2.0f * input[n];
  PackF2 cv;
  cv.f.x = tanhf(x * W1[2 * fp]);
  cv.f.y = tanhf(x * W1[2 * fp + 1]);
  g_t1f[i] = cv.u;
}

// ---------------------------------------------------------------------------
// Fused phase-2 + next-tile-mask1 generation. GEN=false for the last tile.
// sX1 slots are per-thread private: the caller read all 32 before any store.
// ---------------------------------------------------------------------------
template<bool GEN>
__device__ __forceinline__ float phase2_fn(
    unsigned base, unsigned basen, const ull (&x1p)[NF / 2],
    const float* __restrict__ sW2, const float* __restrict__ Wf,
    ull* __restrict__ sX1, const ull* __restrict__ t1col, int tid) {
  float oacc = 0.0f;
#pragma unroll 1
  for (int gp = 0; gp < NF / 2; ++gp) {
    const int gA = 2 * gp, gB = 2 * gp + 1;
    // mask2 chains for this tile (start early, 160-cyc latency each)
    unsigned rA = rng_draw<KM2.a, KM2.b>(base + (unsigned)gA);
    unsigned rB = rng_draw<KM2.a, KM2.b>(base + (unsigned)gB);

    // next tile's mask1 pair (feature pair fp == gp), staged as masked f32x2
    ull stage = 0;
    if (GEN) {
      unsigned r0 = rng_draw<KM1.a, KM1.b>(basen + 2 * (unsigned)gp);
      unsigned r1 = rng_draw<KM1.a, KM1.b>(basen + 2 * (unsigned)gp + 1);
      PackF2 cv;
      cv.u = __ldg(&t1col[gp * SEQ]);
      cv.w[0] &= ~(unsigned)((int)r0 >> 31);
      cv.w[1] &= ~(unsigned)((int)r1 >> 31);
      stage = cv.u;
    }

    const ulonglong2* rowA = reinterpret_cast<const ulonglong2*>(sW2 + gA * NF);
    const ulonglong2* rowB = reinterpret_cast<const ulonglong2*>(sW2 + gB * NF);
    ull a0 = 0, a1 = 0, b0 = 0, b1 = 0;
#pragma unroll
    for (int q = 0; q < 16; ++q) {
      ulonglong2 wa = rowA[q];
      ulonglong2 wb = rowB[q];
      if (q & 1) {
        ffma2(a1, x1p[2 * q + 0], wa.x);
        ffma2(b1, x1p[2 * q + 0], wb.x);
        ffma2(a1, x1p[2 * q + 1], wa.y);
        ffma2(b1, x1p[2 * q + 1], wb.y);
      } else {
        ffma2(a0, x1p[2 * q + 0], wa.x);
        ffma2(b0, x1p[2 * q + 0], wb.x);
        ffma2(a0, x1p[2 * q + 1], wa.y);
        ffma2(b0, x1p[2 * q + 1], wb.y);
      }
    }
    if (GEN) sX1[gp * TB + tid] = stage;   // STS.64

    PackF2 sA; sA.u = addf2(a0, a1);
    PackF2 sB; sB.u = addf2(b0, b1);
    float xA = sA.f.x + sA.f.y;              // *2 folded into W2
    float xB = sB.f.x + sB.f.y;
    float yA = mask_apply(tanh_fast(xA), rA);
    float yB = mask_apply(tanh_fast(xB), rB);
    oacc = fmaf(yA, __ldg(&Wf[gA]), oacc);   // uniform addr, L1-hit
    oacc = fmaf(yB, __ldg(&Wf[gB]), oacc);
  }
  return oacc;
}

// ---------------------------------------------------------------------------
// Main fused kernel. 128 n-lanes x MPB m-samples per block.
// smem: W2 fp32 pre-doubled 16KB + f32x2 staging 32KB = 49152B = 0xc000 cap.
// -> 4 blocks/SM. t1 pairs + Wf via __ldg (L1-resident).
// ---------------------------------------------------------------------------
__global__ void __launch_bounds__(TB, 4)
mc_kernel(const float* __restrict__ W2,
          const float* __restrict__ Wf,
          float* __restrict__ out) {
  __shared__ __align__(16) float sW2[NF * NF];       // [g][f], x2 pre-folded
  __shared__ __align__(16) ull   sX1[(NF / 2) * TB]; // staged masked f32x2

  const int tid = threadIdx.x;
  const int n0  = blockIdx.x * TB;
  const int m0  = blockIdx.y * MPB;
  const int n   = n0 + tid;
  const ull* t1col = g_t1f + n;    // t1col[fp*SEQ] = f32 pair fp for this n

  // W2 -> shared fp32, pre-doubled
  {
    const float4* src = reinterpret_cast<const float4*>(W2);
    float4* dst = reinterpret_cast<float4*>(sW2);
#pragma unroll 1
    for (int i = tid; i < NF * NF / 4; i += TB) {
      float4 v = src[i];
      v.x *= 2.0f; v.y *= 2.0f; v.z *= 2.0f; v.w *= 2.0f;
      dst[i] = v;
    }
  }
  __syncthreads();

  // Pipeline prologue: stage mask1 for tile mi=0 (rolled; dynamic STS ok)
  {
    const unsigned base0 = ((unsigned)m0 * SEQ + (unsigned)n) * NF;
#pragma unroll 1
    for (int fp = 0; fp < NF / 2; ++fp) {
      unsigned r0 = rng_draw<KM1.a, KM1.b>(base0 + 2 * (unsigned)fp);
      unsigned r1 = rng_draw<KM1.a, KM1.b>(base0 + 2 * (unsigned)fp + 1);
      PackF2 cv;
      cv.u = __ldg(&t1col[fp * SEQ]);
      cv.w[0] &= ~(unsigned)((int)r0 >> 31);
      cv.w[1] &= ~(unsigned)((int)r1 >> 31);
      sX1[fp * TB + tid] = cv.u;
    }
  }
  // no sync: sX1 slots are per-thread private

#pragma unroll 1
  for (int mi = 0; mi < MPB; ++mi) {
    const unsigned m = (unsigned)(m0 + mi);
    const unsigned base  = (m * SEQ + (unsigned)n) * NF;
    const unsigned basen = base + (unsigned)(SEQ * NF);   // tile mi+1, same n

    // Load this tile's x1 from staging (already masked f32x2; no converts)
    ull x1p[NF / 2];
#pragma unroll
    for (int fp = 0; fp < NF / 2; ++fp)
      x1p[fp] = sX1[fp * TB + tid];          // LDS.64, conflict-free

    float oacc;
    if (mi != MPB - 1)
      oacc = phase2_fn<true>(base, basen, x1p, sW2, Wf, sX1, t1col, tid);
    else
      oacc = phase2_fn<false>(base, basen, x1p, sW2, Wf, sX1, t1col, tid);
    out[m * SEQ + (unsigned)n] = oacc;
  }
}

// ---------------------------------------------------------------------------
extern "C" void kernel_launch(void* const* d_in, const int* in_sizes, int n_in,
                              void* d_out, int out_size) {
  const float* input = (const float*)d_in[0];   // [2048,1]
  const float* W1    = (const float*)d_in[1];   // [64,1]
  const float* W2    = (const float*)d_in[2];   // [64,64]
  const float* Wf    = (const float*)d_in[3];   // [1,64]
  float* out         = (float*)d_out;           // [1024,2048,1]

  t1_kernel<<<((NF / 2) * SEQ) / 256, 256>>>(input, W1);
  mc_kernel<<<dim3(SEQ / TB, NMC / MPB), TB>>>(W2, Wf, out);
}